// round 10
// baseline (speedup 1.0000x reference)
#include <cuda_runtime.h>
#include <math.h>
#include <cstdio>

#define NP 4096
#define NS 128
#define CH 1024
#define PPOOL (NP * NS)   // elements per pool (float32 reals)

// Zero-fill (float granularity) for pools 3,4 (Fp_b, Fm_b == 0 always).
__global__ void epg_zero1(float* __restrict__ p, int n)
{
    int k = blockIdx.x * blockDim.x + threadIdx.x;
    if (k < n) p[k] = 0.f;
}

__global__ void __launch_bounds__(128, 1)
epg_mt_kernel(const float* __restrict__ flip, const float* __restrict__ phase,
              const float* __restrict__ pT1f, const float* __restrict__ pT2f,
              const float* __restrict__ pT1b, const float* __restrict__ pT2b,
              const float* __restrict__ pkf,  const float* __restrict__ pkb,
              const float* __restrict__ pTR,  const float* __restrict__ pB0,
              const float* __restrict__ pB1,  const float* __restrict__ pwf,
              const float* __restrict__ pwb,
              float* __restrict__ out, int cap_f)
{
    __shared__ float  sc2[CH];
    __shared__ float  skk[CH];
    __shared__ float2 sA[CH];
    __shared__ float2 sC[CH];
    __shared__ float2 shFp[2][4];
    __shared__ float2 shFm[2][4];

    const int i = threadIdx.x;        // state index 0..127
    const int w = i >> 5;             // warp 0..3
    const int l = i & 31;             // lane

    // Loop-invariant per-pool write guards (full pool fits or skip).
    const bool wr0 = (cap_f >= 1 * PPOOL);
    const bool wr1 = (cap_f >= 2 * PPOOL);
    const bool wr2 = (cap_f >= 3 * PPOOL);
    const bool wr5 = (cap_f >= 6 * PPOOL);

    // ---- scalar params / derived constants (redundant per thread, one-time) ----
    const float TR  = pTR[0];
    const float T1f = pT1f[0], T2f = pT2f[0];
    const float T1b = pT1b[0];
    const float kf  = pkf[0],  kb  = pkb[0];
    const float B0  = pB0[0],  B1  = pB1[0];
    const float wf  = pwf[0],  wb  = pwb[0];

    const float E1f = expf(-TR / T1f);
    const float E2f = expf(-TR / T2f);
    const float E1b = expf(-TR / T1b);
    const float scale = TR / 1000.0f;

    // Z update: Zf' = a1*Zf + a2*Zb + Cf ; Zb' = b1*Zb + b2*Zf + Cb
    const float a1 = E1f - kf * scale;
    const float a2 = kb * scale;
    const float Cf = (1.0f - E1f) * wf;
    const float b1 = E1b - kb * scale;
    const float b2 = kf * scale;
    const float Cb = (1.0f - E1b) * wb;

    const float phi = 2.0f * 3.14159265358979323846f * B0 * TR / 1000.0f;
    float rs, rc;
    sincosf(phi, &rs, &rc);           // rot = (rc, rs)

    // ---- initial carry ----
    float2 Fp = make_float2(0.f, 0.f);
    float2 Fm = make_float2(0.f, 0.f);
    float2 Zf = make_float2((i == 0) ? wf : 0.f, 0.f);
    float2 Zb = make_float2((i == 0) ? wb : 0.f, 0.f);

    int buf = 0;

    for (int base = 0; base < NP; base += CH) {
        __syncthreads();   // protect shared const arrays from previous chunk's readers
        // ---- cooperative precompute of per-pulse constants for this chunk ----
        for (int j = i; j < CH; j += 128) {
            float fa = flip[base + j] * B1;
            float ph = phase[base + j];
            float s, c;
            sincosf(0.5f * fa, &s, &c);
            float c2 = c * c, s2 = s * s, cs = c * s;
            float sb, cb;
            sincosf(ph, &sb, &cb);
            sc2[j] = c2;
            skk[j] = c2 - s2;                                  // cos(alpha)
            sA[j]  = make_float2(s2 * (cb * cb - sb * sb),     // s^2 * e^{2i beta}
                                 s2 * (2.f * sb * cb));
            sC[j]  = make_float2(-cs * sb, cs * cb);           // i*c*s*e^{i beta}
        }
        __syncthreads();

        for (int t = 0; t < CH; ++t) {
            const float  c2 = sc2[t];
            const float  ck = skk[t];
            const float2 A  = sA[t];
            const float2 C  = sC[t];

            // --- T2 relaxation (free pool F states; bound F states are always 0) ---
            float fpx = Fp.x * E2f, fpy = Fp.y * E2f;
            float fmx = Fm.x * E2f, fmy = Fm.y * E2f;

            // --- T1 relaxation + exchange (from carry values) ---
            float zfx = a1 * Zf.x + a2 * Zb.x + Cf;
            float zfy = a1 * Zf.y + a2 * Zb.y;
            float zbx = b1 * Zb.x + b2 * Zf.x + Cb;
            float zby = b1 * Zb.y + b2 * Zf.y;

            // --- B0 dephasing: Fp *= rot, Fm *= conj(rot) ---
            float tpx = fpx * rc - fpy * rs;
            float tpy = fpx * rs + fpy * rc;
            float tmx = fmx * rc + fmy * rs;
            float tmy = fmy * rc - fmx * rs;

            // --- RF pulse (free pool) ---
            // Fp' = c2*Fp + A*conj(Fm) + C*Zf
            float Fpn_x = c2 * tpx + A.x * tmx + A.y * tmy + C.x * zfx - C.y * zfy;
            float Fpn_y = c2 * tpy + A.y * tmx - A.x * tmy + C.x * zfy + C.y * zfx;
            // Fm' = conj(A)*conj(Fp) + c2*Fm + conj(C)*Zf
            float Fmn_x =  A.x * tpx - A.y * tpy + c2 * tmx + C.x * zfx + C.y * zfy;
            float Fmn_y = -A.x * tpy - A.y * tpx + c2 * tmy + C.x * zfy - C.y * zfx;
            // Zf' = conj(C)*Fp + C*Fm + (c2-s2)*Zf
            float Zfn_x = C.x * tpx + C.y * tpy + C.x * tmx - C.y * tmy + ck * zfx;
            float Zfn_y = C.x * tpy - C.y * tpx + C.x * tmy + C.y * tmx + ck * zfy;

            // --- gradient shift: Fp up (+1), Fm down (-1) ---
            float upx = __shfl_up_sync(0xffffffffu, Fpn_x, 1);
            float upy = __shfl_up_sync(0xffffffffu, Fpn_y, 1);
            float dnx = __shfl_down_sync(0xffffffffu, Fmn_x, 1);
            float dny = __shfl_down_sync(0xffffffffu, Fmn_y, 1);

            if (l == 31) shFp[buf][w] = make_float2(Fpn_x, Fpn_y);
            if (l == 0)  shFm[buf][w] = make_float2(Fmn_x, Fmn_y);
            __syncthreads();
            if (l == 0 && w > 0) {
                float2 v = shFp[buf][w - 1];
                upx = v.x; upy = v.y;
            }
            if (l == 31) {
                if (w < 3) {
                    float2 v = shFm[buf][w + 1];
                    dnx = v.x; dny = v.y;
                } else {
                    dnx = 0.f; dny = 0.f;
                }
            }
            if (i == 0) { upx = 0.f; upy = 0.f; }

            Fp = make_float2(upx, upy);
            Fm = make_float2(dnx, dny);
            Zf = make_float2(Zfn_x, Zfn_y);
            Zb = make_float2(zbx, zby);

            // --- store REAL PARTS of post-shift carry (float32 output) ---
            const int idx = (base + t) * NS + i;
            if (wr0) out[idx]             = Fp.x;
            if (wr1) out[PPOOL + idx]     = Fm.x;
            if (wr2) out[2 * PPOOL + idx] = Zf.x;
            if (wr5) out[5 * PPOOL + idx] = Zb.x;

            buf ^= 1;
        }
    }
}

extern "C" void kernel_launch(void* const* d_in, const int* in_sizes, int n_in,
                              void* d_out, int out_size)
{
    fprintf(stderr, "[diag] n_in=%d out_size=%d\n", n_in, out_size);
    fflush(stderr);
    (void)in_sizes; (void)n_in;

    // Confirmed by R9 diag: d_in[0]=flip(4096), d_in[1]=phases(4096), then
    // scalars in dict-insertion order.
    const float* flip  = (const float*)d_in[0];
    const float* phase = (const float*)d_in[1];
    const float* T1f   = (const float*)d_in[2];
    const float* T2f   = (const float*)d_in[3];
    const float* T1b   = (const float*)d_in[4];
    const float* T2b   = (const float*)d_in[5];
    const float* kf    = (const float*)d_in[6];
    const float* kb    = (const float*)d_in[7];
    const float* TR    = (const float*)d_in[8];
    // d_in[9] = TE (unused by the reference math)
    const float* B0    = (const float*)d_in[10];
    const float* B1    = (const float*)d_in[11];
    const float* wf    = (const float*)d_in[12];
    const float* wb    = (const float*)d_in[13];

    // Output: out_size float32 elements = (6, NP, NS) real parts. Buffer is
    // exactly out_size*4 bytes — every store below is clamped to that.
    const int cap_f = out_size;

    // Zero-fill pools 3,4 (Fp_b, Fm_b identically zero), clipped to capacity.
    long long z_lo = (long long)3 * PPOOL;
    long long z_hi = (long long)5 * PPOOL;
    if (z_hi > (long long)cap_f) z_hi = cap_f;
    if (z_hi > z_lo) {
        int n = (int)(z_hi - z_lo);
        epg_zero1<<<(n + 255) / 256, 256>>>((float*)d_out + z_lo, n);
    }

    epg_mt_kernel<<<1, 128>>>(flip, phase, T1f, T2f, T1b, T2b, kf, kb,
                              TR, B0, B1, wf, wb, (float*)d_out, cap_f);
}

// round 11
// speedup vs baseline: 3.0826x; 3.0826x over previous
#include <cuda_runtime.h>
#include <math.h>

#define NP 4096
#define NS 128
#define CH 512
#define PPOOL (NP * NS)   // elements per pool (float32 reals)

// Zero-fill for pools 3,4 (Fp_b, Fm_b identically zero).
__global__ void epg_zero1(float* __restrict__ p, int n)
{
    int k = blockIdx.x * blockDim.x + threadIdx.x;
    if (k < n) p[k] = 0.f;
}

__global__ void __launch_bounds__(128, 1)
epg_mt_kernel(const float* __restrict__ flip, const float* __restrict__ phase,
              const float* __restrict__ pT1f, const float* __restrict__ pT2f,
              const float* __restrict__ pT1b, const float* __restrict__ pT2b,
              const float* __restrict__ pkf,  const float* __restrict__ pkb,
              const float* __restrict__ pTR,  const float* __restrict__ pB0,
              const float* __restrict__ pB1,  const float* __restrict__ pwf,
              const float* __restrict__ pwb,
              float* __restrict__ out)
{
    // Per-pulse fused constants: k0=(P1x,P1y,P2x,P2y), k1=(Cx,Cy,Q1x,Q1y), ck
    __shared__ float4 sk0[CH + 1];
    __shared__ float4 sk1[CH + 1];
    __shared__ float  sck[CH + 1];
    // Ping-pong state exchange buffers for the +-1 gradient shift
    __shared__ float2 shFp[2][NS];
    __shared__ float2 shFm[2][NS];

    const int i = threadIdx.x;                 // state 0..127

    // ---- scalar params / derived constants ----
    const float TR  = pTR[0];
    const float T1f = pT1f[0], T2f = pT2f[0];
    const float T1b = pT1b[0];
    const float kf  = pkf[0],  kb  = pkb[0];
    const float B0  = pB0[0],  B1  = pB1[0];
    const float wf  = pwf[0],  wb  = pwb[0];

    const float E1f = expf(-TR / T1f);
    const float E2f = expf(-TR / T2f);
    const float E1b = expf(-TR / T1b);
    const float scale = TR / 1000.0f;

    // Zf' = a1*Zf + a2*Zb + Cf ; Zb' = b1*Zb + b2*Zf + Cb
    const float a1 = E1f - kf * scale;
    const float a2 = kb * scale;
    const float Cf = (1.0f - E1f) * wf;
    const float b1 = E1b - kb * scale;
    const float b2 = kf * scale;
    const float Cb = (1.0f - E1b) * wb;

    const float phi = 2.0f * 3.14159265358979323846f * B0 * TR / 1000.0f;
    float rs, rc;
    sincosf(phi, &rs, &rc);
    const float Rx = E2f * rc;     // R = E2f * e^{i phi}  (relax+rot fused)
    const float Ry = E2f * rs;

    // ---- initial carry ----
    float2 Fp = make_float2(0.f, 0.f);
    float2 Fm = make_float2(0.f, 0.f);
    float2 Zf = make_float2((i == 0) ? wf : 0.f, 0.f);
    float2 Zb = make_float2((i == 0) ? wb : 0.f, 0.f);

    const bool is0   = (i == 0);
    const bool is127 = (i == NS - 1);
    const int  iprev = (i + NS - 1) & (NS - 1);
    const int  inext = (i + 1) & (NS - 1);

    // Rotated-column output pointers: stores land post-shift without waiting
    // for the shift itself. Thread 127 writes the mandatory 0 into col 0 of
    // pool0; thread 0 writes the mandatory 0 into col 127 of pool1.
    float* p0 = out + inext;                 // pool0: Re(Fp) post-shift
    float* p1 = out + PPOOL + iprev;         // pool1: Re(Fm) post-shift
    float* p2 = out + 2 * PPOOL + i;         // pool2: Re(Zf)
    float* p5 = out + 5 * PPOOL + i;         // pool5: Re(Zb)

    int b = 0;

    for (int base = 0; base < NP; base += CH) {
        __syncthreads();   // previous chunk's const reads are done
        // ---- cooperative precompute of fused per-pulse constants ----
        for (int j = i; j < CH; j += 128) {
            float fa = flip[base + j] * B1;
            float ph = phase[base + j];
            float s, c;
            sincosf(0.5f * fa, &s, &c);
            float c2 = c * c, s2 = s * s, cs = c * s;
            float sb, cb;
            sincosf(ph, &sb, &cb);
            // A = s2*e^{2i ph};  C = i*cs*e^{i ph}
            float Ax = s2 * (cb * cb - sb * sb);
            float Ay = s2 * (2.f * sb * cb);
            float Cx = -cs * sb;
            float Cy =  cs * cb;
            // P1 = c2*R ; P2 = A*R ; Q1 = conj(C)*R  (Q2 = conj(Q1))
            sk0[j] = make_float4(c2 * Rx, c2 * Ry,
                                 Ax * Rx - Ay * Ry, Ax * Ry + Ay * Rx);
            sk1[j] = make_float4(Cx, Cy,
                                 Cx * Rx + Cy * Ry, Cx * Ry - Cy * Rx);
            sck[j] = c2 - s2;
        }
        __syncthreads();

        float4 k0 = sk0[0];
        float4 k1 = sk1[0];
        float  ck = sck[0];

        #pragma unroll 2
        for (int t = 0; t < CH; ++t) {
            // prefetch next iteration's constants (consumed next iter)
            float4 n0  = sk0[t + 1];
            float4 n1  = sk1[t + 1];
            float  nck = sck[t + 1];

            const float P1x = k0.x, P1y = k0.y, P2x = k0.z, P2y = k0.w;
            const float Cx  = k1.x, Cy  = k1.y, Q1x = k1.z, Q1y = k1.w;

            // --- T1 relaxation + exchange ---
            float zfx = fmaf(a1, Zf.x, fmaf(a2, Zb.x, Cf));
            float zfy = fmaf(a1, Zf.y, a2 * Zb.y);
            float zbx = fmaf(b1, Zb.x, fmaf(b2, Zf.x, Cb));
            float zby = fmaf(b1, Zb.y, b2 * Zf.y);

            // --- fused relax+rot+RF ---
            // Fpn = P1*Fp + P2*conj(Fm) + C*zf
            float Fpn_x = P1x*Fp.x - P1y*Fp.y + P2x*Fm.x + P2y*Fm.y + Cx*zfx - Cy*zfy;
            float Fpn_y = P1x*Fp.y + P1y*Fp.x - P2x*Fm.y + P2y*Fm.x + Cx*zfy + Cy*zfx;
            // Fmn = conj(P2)*conj(Fp) + conj(P1)*Fm + conj(C)*zf
            float Fmn_x =  P2x*Fp.x - P2y*Fp.y + P1x*Fm.x + P1y*Fm.y + Cx*zfx + Cy*zfy;
            float Fmn_y = -P2x*Fp.y - P2y*Fp.x + P1x*Fm.y - P1y*Fm.x + Cx*zfy - Cy*zfx;
            // Zfn = Q1*Fp + conj(Q1)*Fm + ck*zf
            float Zfn_x = Q1x*Fp.x - Q1y*Fp.y + Q1x*Fm.x + Q1y*Fm.y + ck*zfx;
            float Zfn_y = Q1x*Fp.y + Q1y*Fp.x + Q1x*Fm.y - Q1y*Fm.x + ck*zfy;

            // --- global stores: rotated columns give post-shift layout, all
            //     issued immediately (off the serial dependency chain) ---
            p0[0] = is127 ? 0.f : Fpn_x;
            p1[0] = is0   ? 0.f : Fmn_x;
            p2[0] = Zfn_x;
            p5[0] = zbx;
            p0 += NS; p1 += NS; p2 += NS; p5 += NS;

            // --- gradient shift via ping-pong shared exchange (branch-free) ---
            shFp[b][i] = make_float2(Fpn_x, Fpn_y);
            shFm[b][i] = make_float2(Fmn_x, Fmn_y);
            __syncthreads();
            float2 pv = shFp[b][iprev];
            float2 mv = shFm[b][inext];
            Fp = is0   ? make_float2(0.f, 0.f) : pv;
            Fm = is127 ? make_float2(0.f, 0.f) : mv;
            Zf = make_float2(Zfn_x, Zfn_y);
            Zb = make_float2(zbx, zby);

            k0 = n0; k1 = n1; ck = nck;
            b ^= 1;
        }
    }
}

extern "C" void kernel_launch(void* const* d_in, const int* in_sizes, int n_in,
                              void* d_out, int out_size)
{
    (void)in_sizes; (void)n_in;
    // Confirmed interface (R9/R10 diag): arrays at 0,1; scalars dict-order;
    // out = (6, NP, NS) float32 real parts, out_size = 6*PPOOL.
    const float* flip  = (const float*)d_in[0];
    const float* phase = (const float*)d_in[1];
    const float* T1f   = (const float*)d_in[2];
    const float* T2f   = (const float*)d_in[3];
    const float* T1b   = (const float*)d_in[4];
    const float* T2b   = (const float*)d_in[5];
    const float* kf    = (const float*)d_in[6];
    const float* kb    = (const float*)d_in[7];
    const float* TR    = (const float*)d_in[8];
    // d_in[9] = TE (unused by the reference math)
    const float* B0    = (const float*)d_in[10];
    const float* B1    = (const float*)d_in[11];
    const float* wf    = (const float*)d_in[12];
    const float* wb    = (const float*)d_in[13];

    // Zero-fill pools 3,4 (identically zero), clamped to buffer size.
    long long z_lo = (long long)3 * PPOOL;
    long long z_hi = (long long)5 * PPOOL;
    if (z_hi > (long long)out_size) z_hi = out_size;
    if (z_hi > z_lo) {
        int n = (int)(z_hi - z_lo);
        epg_zero1<<<(n + 255) / 256, 256>>>((float*)d_out + z_lo, n);
    }

    epg_mt_kernel<<<1, 128>>>(flip, phase, T1f, T2f, T1b, T2b, kf, kb,
                              TR, B0, B1, wf, wb, (float*)d_out);
}